// round 1
// baseline (speedup 1.0000x reference)
#include <cuda_runtime.h>

#define IMH 2048
#define IMW 4096
#define TS  32          // output tile (32x32 pixels per block)
#define SH  40          // smem region rows
#define SW  40          // smem region cols
#define SSTR (SW*3)     // smem row stride in floats (120)

// Catmull-Rom (Keys a=-0.5) weights for taps at offsets {-1,0,1,2} from floor,
// as a function of the fractional part f in [0,1). Algebraically identical to
// the reference's piecewise cubic.
__device__ __forceinline__ void catmull(float f, float& w0, float& w1, float& w2, float& w3)
{
    float f2 = f * f;
    float f3 = f2 * f;
    w0 = 0.5f * (-f3 + 2.0f * f2 - f);
    w1 = 0.5f * (3.0f * f3 - 5.0f * f2 + 2.0f);
    w2 = 0.5f * (-3.0f * f3 + 4.0f * f2 + f);
    w3 = 0.5f * (f3 - f2);
}

// Control-point weights for the 3-point spline axis: for coordinate u in [0,2],
// 4 taps clipped to [0,2], accumulated into 3 bins (matches reference's
// scatter-add construction of the upsample matrix row).
__device__ __forceinline__ void ctrl_weights(float u, float b[3])
{
    float fi = floorf(u);
    int   i0 = (int)fi;
    float f  = u - fi;
    float w0, w1, w2, w3;
    catmull(f, w0, w1, w2, w3);
    b[0] = 0.0f; b[1] = 0.0f; b[2] = 0.0f;
    float w[4] = {w0, w1, w2, w3};
#pragma unroll
    for (int a = 0; a < 4; a++) {
        int j = i0 - 1 + a;
        j = j < 0 ? 0 : (j > 2 ? 2 : j);
        if (j == 0) b[0] += w[a];
        else if (j == 1) b[1] += w[a];
        else b[2] += w[a];
    }
}

__global__ __launch_bounds__(256)
void elastic_kernel(const float* __restrict__ img,
                    const float* __restrict__ dctrl,  // (2,3,3) raw N(0,1); x5 applied here
                    float* __restrict__ out)
{
    __shared__ float tile[SH * SSTR];   // 19200 B
    __shared__ float sGx[TS][6];        // per-x: 5 * (D[d,j,:] . Bx) for d=0..1, j=0..2
    __shared__ float sBy[TS][3];        // per-y: By control weights
    __shared__ int   sred[32];

    const int tx  = threadIdx.x;        // 0..31
    const int ty  = threadIdx.y;        // 0..7
    const int tid = ty * 32 + tx;
    const int bx0 = blockIdx.x * TS;
    const int by0 = blockIdx.y * TS;

    // ---- per-tile precompute of separable spline factors ----
    if (tid < 32) {
        int x = bx0 + tid;
        float u = (2.0f * (float)x) / 4095.0f;
        float b[3];
        ctrl_weights(u, b);
#pragma unroll
        for (int d = 0; d < 2; d++)
#pragma unroll
            for (int j = 0; j < 3; j++) {
                const float* Dr = dctrl + d * 9 + j * 3;
                sGx[tid][d * 3 + j] = 5.0f * (Dr[0] * b[0] + Dr[1] * b[1] + Dr[2] * b[2]);
            }
    } else if (tid < 64) {
        int ly = tid - 32;
        int y  = by0 + ly;
        float u = (2.0f * (float)y) / 2047.0f;
        float b[3];
        ctrl_weights(u, b);
        sBy[ly][0] = b[0]; sBy[ly][1] = b[1]; sBy[ly][2] = b[2];
    }
    __syncthreads();

    // ---- per-pixel displacement, warp coords, weights (4 pixels/thread, y-strided) ----
    float wya[4][4], wxa[4][4];
    int   riy[4], rix[4];
    int mnY =  0x7fffffff, mxY = -0x7fffffff;
    int mnX =  0x7fffffff, mxX = -0x7fffffff;

    float gx0 = sGx[tx][0], gx1 = sGx[tx][1], gx2 = sGx[tx][2];
    float gx3 = sGx[tx][3], gx4 = sGx[tx][4], gx5 = sGx[tx][5];

#pragma unroll
    for (int k = 0; k < 4; k++) {
        int ly = ty + 8 * k;
        float b0 = sBy[ly][0], b1 = sBy[ly][1], b2 = sBy[ly][2];
        float dy = b0 * gx0 + b1 * gx1 + b2 * gx2;
        float dx = b0 * gx3 + b1 * gx4 + b2 * gx5;
        float yy = (float)(by0 + ly) + dy;
        float xx = (float)(bx0 + tx) + dx;
        float fy = floorf(yy);
        float fx = floorf(xx);
        int iy = (int)fy;
        int ix = (int)fx;
        catmull(yy - fy, wya[k][0], wya[k][1], wya[k][2], wya[k][3]);
        catmull(xx - fx, wxa[k][0], wxa[k][1], wxa[k][2], wxa[k][3]);
        riy[k] = iy; rix[k] = ix;
        mnY = min(mnY, iy); mxY = max(mxY, iy);
        mnX = min(mnX, ix); mxX = max(mxX, ix);
    }

    // ---- block reduce min/max of tap window ----
#pragma unroll
    for (int o = 16; o; o >>= 1) {
        mnY = min(mnY, __shfl_xor_sync(0xffffffffu, mnY, o));
        mxY = max(mxY, __shfl_xor_sync(0xffffffffu, mxY, o));
        mnX = min(mnX, __shfl_xor_sync(0xffffffffu, mnX, o));
        mxX = max(mxX, __shfl_xor_sync(0xffffffffu, mxX, o));
    }
    int wrp = tid >> 5;
    if ((tid & 31) == 0) {
        sred[wrp]      = mnY;
        sred[8 + wrp]  = mxY;
        sred[16 + wrp] = mnX;
        sred[24 + wrp] = mxX;
    }
    __syncthreads();
    mnY = sred[0]; mxY = sred[8]; mnX = sred[16]; mxX = sred[24];
#pragma unroll
    for (int j = 1; j < 8; j++) {
        mnY = min(mnY, sred[j]);
        mxY = max(mxY, sred[8 + j]);
        mnX = min(mnX, sred[16 + j]);
        mxX = max(mxX, sred[24 + j]);
    }

    const int y0 = mnY - 1, x0 = mnX - 1;
    const int RH = mxY - mnY + 4;
    const int RW = mxX - mnX + 4;
    const bool useS = (RH <= SH) && (RW <= SW);   // uniform across block

    // ---- cooperative clamped tile load (edge-clamp folded into load) ----
    if (useS) {
        for (int r = ty; r < RH; r += 8) {
            int gy = min(max(y0 + r, 0), IMH - 1);
            const float* src = img + (size_t)gy * (IMW * 3);
            for (int c = tx; c < RW; c += 32) {
                int gx = min(max(x0 + c, 0), IMW - 1);
                const float* s = src + gx * 3;
                float* d = &tile[r * SSTR + c * 3];
                d[0] = s[0]; d[1] = s[1]; d[2] = s[2];
            }
        }
    }
    __syncthreads();

    // ---- gather + separable 4x4 accumulation, write out ----
    float* op = out + ((size_t)by0 * IMW + bx0) * 3;

#pragma unroll
    for (int k = 0; k < 4; k++) {
        int ly = ty + 8 * k;
        float a0 = 0.0f, a1 = 0.0f, a2 = 0.0f;
        float u0 = wxa[k][0], u1 = wxa[k][1], u2 = wxa[k][2], u3 = wxa[k][3];

        if (useS) {
            int br = riy[k] - 1 - y0;
            int bc = rix[k] - 1 - x0;
            const float* base = &tile[br * SSTR + bc * 3];
#pragma unroll
            for (int a = 0; a < 4; a++) {
                const float* rp = base + a * SSTR;
                float r0 = u0 * rp[0] + u1 * rp[3] + u2 * rp[6] + u3 * rp[9];
                float r1 = u0 * rp[1] + u1 * rp[4] + u2 * rp[7] + u3 * rp[10];
                float r2 = u0 * rp[2] + u1 * rp[5] + u2 * rp[8] + u3 * rp[11];
                a0 = fmaf(wya[k][a], r0, a0);
                a1 = fmaf(wya[k][a], r1, a1);
                a2 = fmaf(wya[k][a], r2, a2);
            }
        } else {
            // pathological displacement range: direct clamped global gather
#pragma unroll
            for (int a = 0; a < 4; a++) {
                int gy = min(max(riy[k] - 1 + a, 0), IMH - 1);
                const float* src = img + (size_t)gy * (IMW * 3);
                float r0 = 0.0f, r1 = 0.0f, r2 = 0.0f;
#pragma unroll
                for (int b = 0; b < 4; b++) {
                    int gx = min(max(rix[k] - 1 + b, 0), IMW - 1);
                    float wb = wxa[k][b];
                    const float* s = src + gx * 3;
                    r0 = fmaf(wb, s[0], r0);
                    r1 = fmaf(wb, s[1], r1);
                    r2 = fmaf(wb, s[2], r2);
                }
                a0 = fmaf(wya[k][a], r0, a0);
                a1 = fmaf(wya[k][a], r1, a1);
                a2 = fmaf(wya[k][a], r2, a2);
            }
        }

        float* o = op + ((size_t)ly * IMW + tx) * 3;
        o[0] = a0; o[1] = a1; o[2] = a2;
    }
}

extern "C" void kernel_launch(void* const* d_in, const int* in_sizes, int n_in,
                              void* d_out, int out_size)
{
    const float* img   = (const float*)d_in[0];
    const float* dctrl = (const float*)d_in[1];
    if (n_in >= 2 && in_sizes[0] == 18) {   // defensive: displacement listed first
        img   = (const float*)d_in[1];
        dctrl = (const float*)d_in[0];
    }
    dim3 grid(IMW / TS, IMH / TS);
    dim3 block(32, 8);
    elastic_kernel<<<grid, block>>>(img, dctrl, (float*)d_out);
}

// round 4
// speedup vs baseline: 1.2298x; 1.2298x over previous
#include <cuda_runtime.h>

#define IMH 2048
#define IMW 4096
#define TS  32          // output tile (32x32 pixels per block)
#define SH  40          // smem region rows
#define SW  40          // smem region cols
#define SSTR (SW*3)     // smem row stride in floats (120)

// Catmull-Rom (Keys a=-0.5) weights for taps at offsets {-1,0,1,2} from floor,
// as a function of the fractional part f in [0,1). Algebraically identical to
// the reference's piecewise cubic.
__device__ __forceinline__ void catmull(float f, float& w0, float& w1, float& w2, float& w3)
{
    float f2 = f * f;
    float f3 = f2 * f;
    w0 = 0.5f * (-f3 + 2.0f * f2 - f);
    w1 = 0.5f * (3.0f * f3 - 5.0f * f2 + 2.0f);
    w2 = 0.5f * (-3.0f * f3 + 4.0f * f2 + f);
    w3 = 0.5f * (f3 - f2);
}

// Control-point weights for the 3-point spline axis: 4 taps clipped to [0,2],
// accumulated into 3 bins (matches reference's scatter-add B construction).
__device__ __forceinline__ void ctrl_weights(float u, float b[3])
{
    float fi = floorf(u);
    int   i0 = (int)fi;
    float f  = u - fi;
    float w0, w1, w2, w3;
    catmull(f, w0, w1, w2, w3);
    b[0] = 0.0f; b[1] = 0.0f; b[2] = 0.0f;
    float w[4] = {w0, w1, w2, w3};
#pragma unroll
    for (int a = 0; a < 4; a++) {
        int j = i0 - 1 + a;
        j = j < 0 ? 0 : (j > 2 ? 2 : j);
        if (j == 0) b[0] += w[a];
        else if (j == 1) b[1] += w[a];
        else b[2] += w[a];
    }
}

__global__ __launch_bounds__(256, 5)
void elastic_kernel(const float* __restrict__ img,
                    const float* __restrict__ dctrl,  // (2,3,3) raw N(0,1); x5 applied here
                    float* __restrict__ out)
{
    __shared__ float tile[SH * SSTR];   // 19200 B
    __shared__ float sGx[TS][6];        // per-x: 5 * (D[d,j,:] . Bx) for d=0..1, j=0..2
    __shared__ float sBy[TS][3];        // per-y: By control weights
    __shared__ int   sred[32];

    const int tx  = threadIdx.x;        // 0..31
    const int ty  = threadIdx.y;        // 0..7
    const int tid = ty * 32 + tx;
    const int bx0 = blockIdx.x * TS;
    const int by0 = blockIdx.y * TS;

    // ---- per-tile precompute of separable spline factors ----
    if (tid < 32) {
        int x = bx0 + tid;
        float u = (2.0f * (float)x) / 4095.0f;
        float b[3];
        ctrl_weights(u, b);
#pragma unroll
        for (int d = 0; d < 2; d++)
#pragma unroll
            for (int j = 0; j < 3; j++) {
                const float* Dr = dctrl + d * 9 + j * 3;
                sGx[tid][d * 3 + j] = 5.0f * (Dr[0] * b[0] + Dr[1] * b[1] + Dr[2] * b[2]);
            }
    } else if (tid < 64) {
        int ly = tid - 32;
        int y  = by0 + ly;
        float u = (2.0f * (float)y) / 2047.0f;
        float b[3];
        ctrl_weights(u, b);
        sBy[ly][0] = b[0]; sBy[ly][1] = b[1]; sBy[ly][2] = b[2];
    }
    __syncthreads();

    // ---- per-pixel displacement -> tap index + fractional part only ----
    // (weights are recomputed inside the gather loop to keep registers low)
    float ffy[4], ffx[4];
    int   riy[4], rix[4];
    int mnY =  0x7fffffff, mxY = -0x7fffffff;
    int mnX =  0x7fffffff, mxX = -0x7fffffff;

    {
        float gx0 = sGx[tx][0], gx1 = sGx[tx][1], gx2 = sGx[tx][2];
        float gx3 = sGx[tx][3], gx4 = sGx[tx][4], gx5 = sGx[tx][5];

#pragma unroll
        for (int k = 0; k < 4; k++) {
            int ly = ty + 8 * k;
            float b0 = sBy[ly][0], b1 = sBy[ly][1], b2 = sBy[ly][2];
            float dy = b0 * gx0 + b1 * gx1 + b2 * gx2;
            float dx = b0 * gx3 + b1 * gx4 + b2 * gx5;
            float yy = (float)(by0 + ly) + dy;
            float xx = (float)(bx0 + tx) + dx;
            float fy = floorf(yy);
            float fx = floorf(xx);
            int iy = (int)fy;
            int ix = (int)fx;
            ffy[k] = yy - fy;
            ffx[k] = xx - fx;
            riy[k] = iy; rix[k] = ix;
            mnY = min(mnY, iy); mxY = max(mxY, iy);
            mnX = min(mnX, ix); mxX = max(mxX, ix);
        }
    }

    // ---- block reduce min/max of tap window ----
#pragma unroll
    for (int o = 16; o; o >>= 1) {
        mnY = min(mnY, __shfl_xor_sync(0xffffffffu, mnY, o));
        mxY = max(mxY, __shfl_xor_sync(0xffffffffu, mxY, o));
        mnX = min(mnX, __shfl_xor_sync(0xffffffffu, mnX, o));
        mxX = max(mxX, __shfl_xor_sync(0xffffffffu, mxX, o));
    }
    int wrp = tid >> 5;
    if ((tid & 31) == 0) {
        sred[wrp]      = mnY;
        sred[8 + wrp]  = mxY;
        sred[16 + wrp] = mnX;
        sred[24 + wrp] = mxX;
    }
    __syncthreads();
    mnY = sred[0]; mxY = sred[8]; mnX = sred[16]; mxX = sred[24];
#pragma unroll
    for (int j = 1; j < 8; j++) {
        mnY = min(mnY, sred[j]);
        mxY = max(mxY, sred[8 + j]);
        mnX = min(mnX, sred[16 + j]);
        mxX = max(mxX, sred[24 + j]);
    }

    const int y0 = mnY - 1, x0 = mnX - 1;
    const int RH = mxY - mnY + 4;
    const int RW = mxX - mnX + 4;
    const bool useS = (RH <= SH) && (RW <= SW);   // uniform across block

    // ---- cooperative clamped tile load (edge-clamp folded into load) ----
    if (useS) {
        for (int r = ty; r < RH; r += 8) {
            int gy = min(max(y0 + r, 0), IMH - 1);
            const float* src = img + (size_t)gy * (IMW * 3);
            for (int c = tx; c < RW; c += 32) {
                int gx = min(max(x0 + c, 0), IMW - 1);
                const float* s = src + gx * 3;
                float* d = &tile[r * SSTR + c * 3];
                d[0] = s[0]; d[1] = s[1]; d[2] = s[2];
            }
        }
    }
    __syncthreads();

    // ---- gather + separable 4x4 accumulation, write out ----
    float* op = out + ((size_t)by0 * IMW + bx0) * 3;

#pragma unroll
    for (int k = 0; k < 4; k++) {
        int ly = ty + 8 * k;
        float a0 = 0.0f, a1 = 0.0f, a2 = 0.0f;

        float u0, u1, u2, u3;
        catmull(ffx[k], u0, u1, u2, u3);
        float v0, v1, v2, v3;
        catmull(ffy[k], v0, v1, v2, v3);

        if (useS) {
            int br = riy[k] - 1 - y0;
            int bc = rix[k] - 1 - x0;
            const float* base = &tile[br * SSTR + bc * 3];
            float wv[4] = {v0, v1, v2, v3};
#pragma unroll
            for (int a = 0; a < 4; a++) {
                const float* rp = base + a * SSTR;
                float r0 = u0 * rp[0] + u1 * rp[3] + u2 * rp[6] + u3 * rp[9];
                float r1 = u0 * rp[1] + u1 * rp[4] + u2 * rp[7] + u3 * rp[10];
                float r2 = u0 * rp[2] + u1 * rp[5] + u2 * rp[8] + u3 * rp[11];
                a0 = fmaf(wv[a], r0, a0);
                a1 = fmaf(wv[a], r1, a1);
                a2 = fmaf(wv[a], r2, a2);
            }
        } else {
            // pathological displacement range: direct clamped global gather
            float wv[4] = {v0, v1, v2, v3};
#pragma unroll
            for (int a = 0; a < 4; a++) {
                int gy = min(max(riy[k] - 1 + a, 0), IMH - 1);
                const float* src = img + (size_t)gy * (IMW * 3);
                float r0 = 0.0f, r1 = 0.0f, r2 = 0.0f;
#pragma unroll
                for (int b = 0; b < 4; b++) {
                    int gx = min(max(rix[k] - 1 + b, 0), IMW - 1);
                    float wb = (b == 0) ? u0 : (b == 1) ? u1 : (b == 2) ? u2 : u3;
                    const float* s = src + gx * 3;
                    r0 = fmaf(wb, s[0], r0);
                    r1 = fmaf(wb, s[1], r1);
                    r2 = fmaf(wb, s[2], r2);
                }
                a0 = fmaf(wv[a], r0, a0);
                a1 = fmaf(wv[a], r1, a1);
                a2 = fmaf(wv[a], r2, a2);
            }
        }

        float* o = op + ((size_t)ly * IMW + tx) * 3;
        o[0] = a0; o[1] = a1; o[2] = a2;
    }
}

extern "C" void kernel_launch(void* const* d_in, const int* in_sizes, int n_in,
                              void* d_out, int out_size)
{
    const float* img   = (const float*)d_in[0];
    const float* dctrl = (const float*)d_in[1];
    if (n_in >= 2 && in_sizes[0] == 18) {   // defensive: displacement listed first
        img   = (const float*)d_in[1];
        dctrl = (const float*)d_in[0];
    }
    dim3 grid(IMW / TS, IMH / TS);
    dim3 block(32, 8);
    elastic_kernel<<<grid, block>>>(img, dctrl, (float*)d_out);
}

// round 8
// speedup vs baseline: 1.4901x; 1.2117x over previous
#include <cuda_runtime.h>

#define IMH 2048
#define IMW 4096
#define TS  32          // output tile (32x32 pixels per block)
#define SH  40          // smem region rows
#define SW  40          // smem region cols
#define SSTR (SW*3)     // smem row stride in floats (120, multiple of 4)

// Catmull-Rom (Keys a=-0.5) weights for taps at offsets {-1,0,1,2} from floor,
// as a function of the fractional part f in [0,1). Algebraically identical to
// the reference's piecewise cubic.
__device__ __forceinline__ void catmull(float f, float& w0, float& w1, float& w2, float& w3)
{
    float f2 = f * f;
    float f3 = f2 * f;
    w0 = 0.5f * (-f3 + 2.0f * f2 - f);
    w1 = 0.5f * (3.0f * f3 - 5.0f * f2 + 2.0f);
    w2 = 0.5f * (-3.0f * f3 + 4.0f * f2 + f);
    w3 = 0.5f * (f3 - f2);
}

// Control-point weights for the 3-point spline axis: 4 taps clipped to [0,2],
// accumulated into 3 bins (matches reference's scatter-add B construction).
__device__ __forceinline__ void ctrl_weights(float u, float b[3])
{
    float fi = floorf(u);
    int   i0 = (int)fi;
    float f  = u - fi;
    float w0, w1, w2, w3;
    catmull(f, w0, w1, w2, w3);
    b[0] = 0.0f; b[1] = 0.0f; b[2] = 0.0f;
    float w[4] = {w0, w1, w2, w3};
#pragma unroll
    for (int a = 0; a < 4; a++) {
        int j = i0 - 1 + a;
        j = j < 0 ? 0 : (j > 2 ? 2 : j);
        if (j == 0) b[0] += w[a];
        else if (j == 1) b[1] += w[a];
        else b[2] += w[a];
    }
}

__global__ __launch_bounds__(256, 5)
void elastic_kernel(const float* __restrict__ img,
                    const float* __restrict__ dctrl,  // (2,3,3) raw N(0,1); x5 applied here
                    float* __restrict__ out)
{
    __shared__ __align__(16) float tile[SH * SSTR];   // 19200 B
    __shared__ float sGx[TS][6];        // per-x: 5 * (D[d,j,:] . Bx) for d=0..1, j=0..2
    __shared__ float sBy[TS][3];        // per-y: By control weights
    __shared__ int   sred[32];

    const int tx  = threadIdx.x;        // 0..31
    const int ty  = threadIdx.y;        // 0..7
    const int tid = ty * 32 + tx;
    const int bx0 = blockIdx.x * TS;
    const int by0 = blockIdx.y * TS;

    // ---- per-tile precompute of separable spline factors ----
    if (tid < 32) {
        int x = bx0 + tid;
        float u = (2.0f * (float)x) / 4095.0f;
        float b[3];
        ctrl_weights(u, b);
#pragma unroll
        for (int d = 0; d < 2; d++)
#pragma unroll
            for (int j = 0; j < 3; j++) {
                const float* Dr = dctrl + d * 9 + j * 3;
                sGx[tid][d * 3 + j] = 5.0f * (Dr[0] * b[0] + Dr[1] * b[1] + Dr[2] * b[2]);
            }
    } else if (tid < 64) {
        int ly = tid - 32;
        int y  = by0 + ly;
        float u = (2.0f * (float)y) / 2047.0f;
        float b[3];
        ctrl_weights(u, b);
        sBy[ly][0] = b[0]; sBy[ly][1] = b[1]; sBy[ly][2] = b[2];
    }
    __syncthreads();

    // ---- per-pixel displacement -> tap index + fractional part only ----
    float ffy[4], ffx[4];
    int   riy[4], rix[4];
    int mnY =  0x7fffffff, mxY = -0x7fffffff;
    int mnX =  0x7fffffff, mxX = -0x7fffffff;

    {
        float gx0 = sGx[tx][0], gx1 = sGx[tx][1], gx2 = sGx[tx][2];
        float gx3 = sGx[tx][3], gx4 = sGx[tx][4], gx5 = sGx[tx][5];

#pragma unroll
        for (int k = 0; k < 4; k++) {
            int ly = ty + 8 * k;
            float b0 = sBy[ly][0], b1 = sBy[ly][1], b2 = sBy[ly][2];
            float dy = b0 * gx0 + b1 * gx1 + b2 * gx2;
            float dx = b0 * gx3 + b1 * gx4 + b2 * gx5;
            float yy = (float)(by0 + ly) + dy;
            float xx = (float)(bx0 + tx) + dx;
            float fy = floorf(yy);
            float fx = floorf(xx);
            int iy = (int)fy;
            int ix = (int)fx;
            ffy[k] = yy - fy;
            ffx[k] = xx - fx;
            riy[k] = iy; rix[k] = ix;
            mnY = min(mnY, iy); mxY = max(mxY, iy);
            mnX = min(mnX, ix); mxX = max(mxX, ix);
        }
    }

    // ---- block reduce min/max of tap window ----
#pragma unroll
    for (int o = 16; o; o >>= 1) {
        mnY = min(mnY, __shfl_xor_sync(0xffffffffu, mnY, o));
        mxY = max(mxY, __shfl_xor_sync(0xffffffffu, mxY, o));
        mnX = min(mnX, __shfl_xor_sync(0xffffffffu, mnX, o));
        mxX = max(mxX, __shfl_xor_sync(0xffffffffu, mxX, o));
    }
    int wrp = tid >> 5;
    if ((tid & 31) == 0) {
        sred[wrp]      = mnY;
        sred[8 + wrp]  = mxY;
        sred[16 + wrp] = mnX;
        sred[24 + wrp] = mxX;
    }
    __syncthreads();
    mnY = sred[0]; mxY = sred[8]; mnX = sred[16]; mxX = sred[24];
#pragma unroll
    for (int j = 1; j < 8; j++) {
        mnY = min(mnY, sred[j]);
        mxY = max(mxY, sred[8 + j]);
        mnX = min(mnX, sred[16 + j]);
        mxX = max(mxX, sred[24 + j]);
    }

    const int y0 = mnY - 1, x0 = mnX - 1;
    const int RH = mxY - mnY + 4;
    const int RW = mxX - mnX + 4;
    const bool useS = (RH <= SH) && (RW <= SW);   // uniform across block

    // ---- cooperative tile load ----
    // Fast path: fully-interior region (no clamping) copied as phase-aligned
    // float4 rows: global float offset aligned down to a 16B boundary, stored
    // at the same phase p in smem (SSTR % 4 == 0 preserves phase per row).
    // The gather below adds p to its base. RW*3 + p must fit in SSTR.
    int p = 0;
    if (useS) {
        bool interior = (y0 >= 0) && (y0 + RH <= IMH) &&
                        (x0 >= 0) && (x0 + RW <= IMW) &&
                        (RW * 3 + 3 <= SSTR);
        if (interior) {
            int g0 = x0 * 3;
            p = g0 & 3;
            int g0a4 = (g0 - p) >> 2;               // float4 index within row
            int n4 = (RW * 3 + p + 3) >> 2;         // float4s per row (<= 30)
            const float4* img4 = (const float4*)img;
            float4* tile4 = (float4*)tile;
            for (int r = ty; r < RH; r += 8) {
                const float4* src = img4 + (size_t)(y0 + r) * (IMW * 3 / 4) + g0a4;
                float4* dst = tile4 + r * (SSTR / 4);
                if (tx < n4) dst[tx] = src[tx];
            }
        } else {
            for (int r = ty; r < RH; r += 8) {
                int gy = min(max(y0 + r, 0), IMH - 1);
                const float* src = img + (size_t)gy * (IMW * 3);
                for (int c = tx; c < RW; c += 32) {
                    int gx = min(max(x0 + c, 0), IMW - 1);
                    const float* s = src + gx * 3;
                    float* d = &tile[r * SSTR + c * 3];
                    d[0] = s[0]; d[1] = s[1]; d[2] = s[2];
                }
            }
        }
    }
    __syncthreads();

    // ---- gather + separable 4x4 accumulation, write out ----
    float* op = out + ((size_t)by0 * IMW + bx0) * 3;

#pragma unroll
    for (int k = 0; k < 4; k++) {
        int ly = ty + 8 * k;
        float a0 = 0.0f, a1 = 0.0f, a2 = 0.0f;

        float u0, u1, u2, u3;
        catmull(ffx[k], u0, u1, u2, u3);
        float v0, v1, v2, v3;
        catmull(ffy[k], v0, v1, v2, v3);

        if (useS) {
            int br = riy[k] - 1 - y0;
            int bc = rix[k] - 1 - x0;
            const float* base = &tile[br * SSTR + bc * 3 + p];
            float wv[4] = {v0, v1, v2, v3};
#pragma unroll
            for (int a = 0; a < 4; a++) {
                const float* rp = base + a * SSTR;
                float r0 = u0 * rp[0] + u1 * rp[3] + u2 * rp[6] + u3 * rp[9];
                float r1 = u0 * rp[1] + u1 * rp[4] + u2 * rp[7] + u3 * rp[10];
                float r2 = u0 * rp[2] + u1 * rp[5] + u2 * rp[8] + u3 * rp[11];
                a0 = fmaf(wv[a], r0, a0);
                a1 = fmaf(wv[a], r1, a1);
                a2 = fmaf(wv[a], r2, a2);
            }
        } else {
            // pathological displacement range: direct clamped global gather
            float wv[4] = {v0, v1, v2, v3};
#pragma unroll
            for (int a = 0; a < 4; a++) {
                int gy = min(max(riy[k] - 1 + a, 0), IMH - 1);
                const float* src = img + (size_t)gy * (IMW * 3);
                float r0 = 0.0f, r1 = 0.0f, r2 = 0.0f;
#pragma unroll
                for (int b = 0; b < 4; b++) {
                    int gx = min(max(rix[k] - 1 + b, 0), IMW - 1);
                    float wb = (b == 0) ? u0 : (b == 1) ? u1 : (b == 2) ? u2 : u3;
                    const float* s = src + gx * 3;
                    r0 = fmaf(wb, s[0], r0);
                    r1 = fmaf(wb, s[1], r1);
                    r2 = fmaf(wb, s[2], r2);
                }
                a0 = fmaf(wv[a], r0, a0);
                a1 = fmaf(wv[a], r1, a1);
                a2 = fmaf(wv[a], r2, a2);
            }
        }

        float* o = op + ((size_t)ly * IMW + tx) * 3;
        o[0] = a0; o[1] = a1; o[2] = a2;
    }
}

extern "C" void kernel_launch(void* const* d_in, const int* in_sizes, int n_in,
                              void* d_out, int out_size)
{
    const float* img   = (const float*)d_in[0];
    const float* dctrl = (const float*)d_in[1];
    if (n_in >= 2 && in_sizes[0] == 18) {   // defensive: displacement listed first
        img   = (const float*)d_in[1];
        dctrl = (const float*)d_in[0];
    }
    dim3 grid(IMW / TS, IMH / TS);
    dim3 block(32, 8);
    elastic_kernel<<<grid, block>>>(img, dctrl, (float*)d_out);
}

// round 12
// speedup vs baseline: 1.4936x; 1.0024x over previous
#include <cuda_runtime.h>

#define IMH 2048
#define IMW 4096
#define TS  32          // output tile (32x32 pixels per block)
#define SH  40          // smem region rows
#define SW  40          // smem region cols
#define SSTR (SW*3)     // smem row stride in floats (120, multiple of 4)

// Catmull-Rom (Keys a=-0.5) weights for taps at offsets {-1,0,1,2} from floor,
// as a function of the fractional part f in [0,1). Algebraically identical to
// the reference's piecewise cubic.
__device__ __forceinline__ void catmull(float f, float& w0, float& w1, float& w2, float& w3)
{
    float f2 = f * f;
    float f3 = f2 * f;
    w0 = 0.5f * (-f3 + 2.0f * f2 - f);
    w1 = 0.5f * (3.0f * f3 - 5.0f * f2 + 2.0f);
    w2 = 0.5f * (-3.0f * f3 + 4.0f * f2 + f);
    w3 = 0.5f * (f3 - f2);
}

// Control-point weights for the 3-point spline axis: 4 taps clipped to [0,2],
// accumulated into 3 bins (matches reference's scatter-add B construction).
__device__ __forceinline__ void ctrl_weights(float u, float b[3])
{
    float fi = floorf(u);
    int   i0 = (int)fi;
    float f  = u - fi;
    float w0, w1, w2, w3;
    catmull(f, w0, w1, w2, w3);
    b[0] = 0.0f; b[1] = 0.0f; b[2] = 0.0f;
    float w[4] = {w0, w1, w2, w3};
#pragma unroll
    for (int a = 0; a < 4; a++) {
        int j = i0 - 1 + a;
        j = j < 0 ? 0 : (j > 2 ? 2 : j);
        if (j == 0) b[0] += w[a];
        else if (j == 1) b[1] += w[a];
        else b[2] += w[a];
    }
}

__global__ __launch_bounds__(256, 6)
void elastic_kernel(const float* __restrict__ img,
                    const float* __restrict__ dctrl,  // (2,3,3) raw N(0,1); x5 applied here
                    float* __restrict__ out)
{
    __shared__ __align__(16) float tile[SH * SSTR];   // 19200 B
    __shared__ float sGx[TS][6];        // per-x: 5 * (D[d,j,:] . Bx) for d=0..1, j=0..2
    __shared__ float sBy[TS][3];        // per-y: By control weights
    __shared__ int   sred[32];
    __shared__ float sFFx[4 * 256];     // per-pixel fractional x (k-major)
    __shared__ float sFFy[4 * 256];     // per-pixel fractional y

    const int tx  = threadIdx.x;        // 0..31
    const int ty  = threadIdx.y;        // 0..7
    const int tid = ty * 32 + tx;
    const int bx0 = blockIdx.x * TS;
    const int by0 = blockIdx.y * TS;

    // ---- per-tile precompute of separable spline factors ----
    if (tid < 32) {
        int x = bx0 + tid;
        float u = (2.0f * (float)x) / 4095.0f;
        float b[3];
        ctrl_weights(u, b);
#pragma unroll
        for (int d = 0; d < 2; d++)
#pragma unroll
            for (int j = 0; j < 3; j++) {
                const float* Dr = dctrl + d * 9 + j * 3;
                sGx[tid][d * 3 + j] = 5.0f * (Dr[0] * b[0] + Dr[1] * b[1] + Dr[2] * b[2]);
            }
    } else if (tid < 64) {
        int ly = tid - 32;
        int y  = by0 + ly;
        float u = (2.0f * (float)y) / 2047.0f;
        float b[3];
        ctrl_weights(u, b);
        sBy[ly][0] = b[0]; sBy[ly][1] = b[1]; sBy[ly][2] = b[2];
    }
    __syncthreads();

    // ---- per-pixel displacement -> tap index + fractional part ----
    // fractional parts go to smem; tap indices packed 2-per-int in regs.
    int rixy[4];                        // ((riy+32)<<16) | (rix+32)
    int mnY =  0x7fffffff, mxY = -0x7fffffff;
    int mnX =  0x7fffffff, mxX = -0x7fffffff;

    {
        float gx0 = sGx[tx][0], gx1 = sGx[tx][1], gx2 = sGx[tx][2];
        float gx3 = sGx[tx][3], gx4 = sGx[tx][4], gx5 = sGx[tx][5];

#pragma unroll
        for (int k = 0; k < 4; k++) {
            int ly = ty + 8 * k;
            float b0 = sBy[ly][0], b1 = sBy[ly][1], b2 = sBy[ly][2];
            float dy = b0 * gx0 + b1 * gx1 + b2 * gx2;
            float dx = b0 * gx3 + b1 * gx4 + b2 * gx5;
            float yy = (float)(by0 + ly) + dy;
            float xx = (float)(bx0 + tx) + dx;
            float fy = floorf(yy);
            float fx = floorf(xx);
            int iy = (int)fy;
            int ix = (int)fx;
            sFFy[k * 256 + tid] = yy - fy;
            sFFx[k * 256 + tid] = xx - fx;
            rixy[k] = ((iy + 32) << 16) | (ix + 32);
            mnY = min(mnY, iy); mxY = max(mxY, iy);
            mnX = min(mnX, ix); mxX = max(mxX, ix);
        }
    }

    // ---- block reduce min/max of tap window ----
#pragma unroll
    for (int o = 16; o; o >>= 1) {
        mnY = min(mnY, __shfl_xor_sync(0xffffffffu, mnY, o));
        mxY = max(mxY, __shfl_xor_sync(0xffffffffu, mxY, o));
        mnX = min(mnX, __shfl_xor_sync(0xffffffffu, mnX, o));
        mxX = max(mxX, __shfl_xor_sync(0xffffffffu, mxX, o));
    }
    int wrp = tid >> 5;
    if ((tid & 31) == 0) {
        sred[wrp]      = mnY;
        sred[8 + wrp]  = mxY;
        sred[16 + wrp] = mnX;
        sred[24 + wrp] = mxX;
    }
    __syncthreads();
    mnY = sred[0]; mxY = sred[8]; mnX = sred[16]; mxX = sred[24];
#pragma unroll
    for (int j = 1; j < 8; j++) {
        mnY = min(mnY, sred[j]);
        mxY = max(mxY, sred[8 + j]);
        mnX = min(mnX, sred[16 + j]);
        mxX = max(mxX, sred[24 + j]);
    }

    const int y0 = mnY - 1, x0 = mnX - 1;
    const int RH = mxY - mnY + 4;
    const int RW = mxX - mnX + 4;
    const bool useS = (RH <= SH) && (RW <= SW);   // uniform across block

    // ---- cooperative tile load ----
    // Fast path: fully-interior region (no clamping) copied as phase-aligned
    // float4 rows: global float offset aligned down to a 16B boundary, stored
    // at the same phase p in smem (SSTR % 4 == 0 preserves phase per row).
    // The gather below adds p to its base. RW*3 + p must fit in SSTR.
    int p = 0;
    if (useS) {
        bool interior = (y0 >= 0) && (y0 + RH <= IMH) &&
                        (x0 >= 0) && (x0 + RW <= IMW) &&
                        (RW * 3 + 3 <= SSTR);
        if (interior) {
            int g0 = x0 * 3;
            p = g0 & 3;
            int g0a4 = (g0 - p) >> 2;               // float4 index within row
            int n4 = (RW * 3 + p + 3) >> 2;         // float4s per row (<= 30)
            const float4* img4 = (const float4*)img;
            float4* tile4 = (float4*)tile;
            for (int r = ty; r < RH; r += 8) {
                const float4* src = img4 + (size_t)(y0 + r) * (IMW * 3 / 4) + g0a4;
                float4* dst = tile4 + r * (SSTR / 4);
                if (tx < n4) dst[tx] = src[tx];
            }
        } else {
            for (int r = ty; r < RH; r += 8) {
                int gy = min(max(y0 + r, 0), IMH - 1);
                const float* src = img + (size_t)gy * (IMW * 3);
                for (int c = tx; c < RW; c += 32) {
                    int gx = min(max(x0 + c, 0), IMW - 1);
                    const float* s = src + gx * 3;
                    float* d = &tile[r * SSTR + c * 3];
                    d[0] = s[0]; d[1] = s[1]; d[2] = s[2];
                }
            }
        }
    }
    __syncthreads();

    // ---- gather + separable 4x4 accumulation, write out ----
    float* op = out + ((size_t)by0 * IMW + bx0) * 3;

#pragma unroll
    for (int k = 0; k < 4; k++) {
        int ly = ty + 8 * k;
        float a0 = 0.0f, a1 = 0.0f, a2 = 0.0f;

        int riy = (rixy[k] >> 16) - 32;
        int rix = (rixy[k] & 0xffff) - 32;

        float u0, u1, u2, u3;
        catmull(sFFx[k * 256 + tid], u0, u1, u2, u3);
        float v0, v1, v2, v3;
        catmull(sFFy[k * 256 + tid], v0, v1, v2, v3);

        if (useS) {
            int br = riy - 1 - y0;
            int bc = rix - 1 - x0;
            const float* base = &tile[br * SSTR + bc * 3 + p];
            float wv[4] = {v0, v1, v2, v3};
#pragma unroll
            for (int a = 0; a < 4; a++) {
                const float* rp = base + a * SSTR;
                float r0 = u0 * rp[0] + u1 * rp[3] + u2 * rp[6] + u3 * rp[9];
                float r1 = u0 * rp[1] + u1 * rp[4] + u2 * rp[7] + u3 * rp[10];
                float r2 = u0 * rp[2] + u1 * rp[5] + u2 * rp[8] + u3 * rp[11];
                a0 = fmaf(wv[a], r0, a0);
                a1 = fmaf(wv[a], r1, a1);
                a2 = fmaf(wv[a], r2, a2);
            }
        } else {
            // pathological displacement range: direct clamped global gather
            float wv[4] = {v0, v1, v2, v3};
#pragma unroll
            for (int a = 0; a < 4; a++) {
                int gy = min(max(riy - 1 + a, 0), IMH - 1);
                const float* src = img + (size_t)gy * (IMW * 3);
                float r0 = 0.0f, r1 = 0.0f, r2 = 0.0f;
#pragma unroll
                for (int b = 0; b < 4; b++) {
                    int gx = min(max(rix - 1 + b, 0), IMW - 1);
                    float wb = (b == 0) ? u0 : (b == 1) ? u1 : (b == 2) ? u2 : u3;
                    const float* s = src + gx * 3;
                    r0 = fmaf(wb, s[0], r0);
                    r1 = fmaf(wb, s[1], r1);
                    r2 = fmaf(wb, s[2], r2);
                }
                a0 = fmaf(wv[a], r0, a0);
                a1 = fmaf(wv[a], r1, a1);
                a2 = fmaf(wv[a], r2, a2);
            }
        }

        float* o = op + ((size_t)ly * IMW + tx) * 3;
        o[0] = a0; o[1] = a1; o[2] = a2;
    }
}

extern "C" void kernel_launch(void* const* d_in, const int* in_sizes, int n_in,
                              void* d_out, int out_size)
{
    const float* img   = (const float*)d_in[0];
    const float* dctrl = (const float*)d_in[1];
    if (n_in >= 2 && in_sizes[0] == 18) {   // defensive: displacement listed first
        img   = (const float*)d_in[1];
        dctrl = (const float*)d_in[0];
    }
    dim3 grid(IMW / TS, IMH / TS);
    dim3 block(32, 8);
    elastic_kernel<<<grid, block>>>(img, dctrl, (float*)d_out);
}